// round 17
// baseline (speedup 1.0000x reference)
#include <cuda_runtime.h>

// CRF NLL: bidirectional bf16 scan, TWO same-direction half-chains fused
// per single warp. bf16 E costs only 64 regs (vs 128 in fp32), making the
// R11 two-chain fusion register-feasible: per step-pair 128 HFMA2 in two
// independent dependency trees (ILP hides FMA + LDS latency), one
// __syncwarp. 512 warps (~0.87/SMSP -> private schedulers).
// Block w<256: forward halves of batches {w, w+256} (P_h).
// Block w>=256: backward co-vector halves of the same batches (u_h).
// answer = log(dot(P_h, u_h)); exact power-of-2 rescaling; raw feats ring,
// exp at consume time.

constexpr int Bb = 512;
constexpr int Ss = 512;
constexpr int Tt = 64;
constexpr int START = Tt - 2;
constexpr int STOP  = Tt - 1;
constexpr int PD    = 4;
constexpr int HALF  = Bb / 2;   // 256
constexpr float LN2 = 0.69314718055994531f;

__device__ float g_meet[Bb][2][68];  // [0]: P_h,64=eF,65=c0,66=goldF ; [1]: u_h,64=eB,65=goldB
__device__ float g_partial[Bb];
__device__ unsigned g_pair[Bb];      // zero-initialized
__device__ unsigned g_count = 0;

static __device__ __forceinline__ unsigned hfma2(unsigned a, unsigned b, unsigned c) {
    unsigned d;
    asm("fma.rn.bf16x2 %0, %1, %2, %3;" : "=r"(d) : "r"(a), "r"(b), "r"(c));
    return d;
}
static __device__ __forceinline__ unsigned hadd2(unsigned a, unsigned b) {
    unsigned d;
    asm("add.rn.bf16x2 %0, %1, %2;" : "=r"(d) : "r"(a), "r"(b));
    return d;
}
static __device__ __forceinline__ unsigned pack_bf2(float lo, float hi) {
    unsigned d;
    asm("cvt.rn.bf16x2.f32 %0, %1, %2;" : "=r"(d) : "f"(hi), "f"(lo));
    return d;
}
static __device__ __forceinline__ float bf_lo(unsigned w) {
    return __uint_as_float(w << 16);
}
static __device__ __forceinline__ float bf_hi(unsigned w) {
    return __uint_as_float(w & 0xFFFF0000u);
}
static __device__ __forceinline__ float ldcg(const float* p) {
    float v;
    asm volatile("ld.global.cg.f32 %0, [%1];" : "=f"(v) : "l"(p));
    return v;
}
static __device__ __forceinline__ float warp_sum(float v) {
    #pragma unroll
    for (int off = 16; off > 0; off >>= 1)
        v += __shfl_xor_sync(0xffffffffu, v, off);
    return v;
}
static __device__ __forceinline__ int warp_sum_i(int v) {
    #pragma unroll
    for (int off = 16; off > 0; off >>= 1)
        v += __shfl_xor_sync(0xffffffffu, v, off);
    return v;
}

__global__ __launch_bounds__(32) void crf_kernel(
    const float* __restrict__ feats,
    const unsigned char* __restrict__ mask8,
    const int* __restrict__ tags,
    const float* __restrict__ trans,
    float* __restrict__ out)
{
    const bool isF = (blockIdx.x < HALF);
    const int  w   = isF ? blockIdx.x : blockIdx.x - HALF;
    const int  bA  = w;
    const int  bB  = w + HALF;
    const int  lane = threadIdx.x;
    const int  to0  = 2 * lane;

    __shared__ __align__(16) unsigned qA[2][Tt / 2], qB[2][Tt / 2];

    // ---- mask layout probe + lengths ----
    const int* mask32 = reinterpret_cast<const int*>(mask8);
    const bool is32 = (mask8[0] == 1 && mask8[1] == 0 && mask8[2] == 0 && mask8[3] == 0);

    int cA = 0, cB = 0;
    #pragma unroll
    for (int k = 0; k < Ss / 32; ++k) {
        int s = lane + k * 32;
        int va = is32 ? mask32[bA * Ss + s] : (int)mask8[bA * Ss + s];
        int vb = is32 ? mask32[bB * Ss + s] : (int)mask8[bB * Ss + s];
        cA += (va != 0);
        cB += (vb != 0);
    }
    const int LA = warp_sum_i(cA);
    const int LB = warp_sum_i(cB);
    const int hA = LA / 2, hB = LB / 2;

    const float* fAp = feats + (size_t)bA * Ss * Tt;
    const float* fBp = feats + (size_t)bB * Ss * Tt;
    const int*   tgA = tags + bA * Ss;
    const int*   tgB = tags + bB * Ss;

    // ---- bf16 E pairs (shared by both chains; orientation per direction) ----
    unsigned E2a[Tt / 2], E2b[Tt / 2];
    if (isF) {
        #pragma unroll
        for (int k = 0; k < Tt / 2; ++k) {
            E2a[k] = pack_bf2(__expf(trans[(2 * k) * Tt + to0]),
                              __expf(trans[(2 * k + 1) * Tt + to0]));
            E2b[k] = pack_bf2(__expf(trans[(2 * k) * Tt + to0 + 1]),
                              __expf(trans[(2 * k + 1) * Tt + to0 + 1]));
        }
    } else {
        #pragma unroll
        for (int k = 0; k < Tt / 2; ++k) {
            E2a[k] = pack_bf2(__expf(trans[to0 * Tt + 2 * k]),
                              __expf(trans[to0 * Tt + 2 * k + 1]));
            E2b[k] = pack_bf2(__expf(trans[(to0 + 1) * Tt + 2 * k]),
                              __expf(trans[(to0 + 1) * Tt + 2 * k + 1]));
        }
    }

    int   eSumA = 0, eSumB = 0;
    int   pbA = 0, pbB = 0;
    float curA0 = 0.f, curA1 = 0.f, curB0 = 0.f, curB1 = 0.f;
    float goldA = 0.f, goldB = 0.f, cA0 = 0.f, cB0 = 0.f;

    // single-chain matvec (tails)
    auto matvec1 = [&](const unsigned* qrow, float& dA, float& dB, unsigned& w0) {
        const uint4* qp = reinterpret_cast<const uint4*>(qrow);
        unsigned a0, a1, a2, a3, b0, b1, b2, b3;
        {
            uint4 v = qp[0];
            w0 = v.x;
            a0 = hfma2(v.x, E2a[0], 0u);  a1 = hfma2(v.y, E2a[1], 0u);
            a2 = hfma2(v.z, E2a[2], 0u);  a3 = hfma2(v.w, E2a[3], 0u);
            b0 = hfma2(v.x, E2b[0], 0u);  b1 = hfma2(v.y, E2b[1], 0u);
            b2 = hfma2(v.z, E2b[2], 0u);  b3 = hfma2(v.w, E2b[3], 0u);
        }
        #pragma unroll
        for (int j = 1; j < 8; ++j) {
            uint4 v = qp[j];
            a0 = hfma2(v.x, E2a[4 * j + 0], a0);
            a1 = hfma2(v.y, E2a[4 * j + 1], a1);
            a2 = hfma2(v.z, E2a[4 * j + 2], a2);
            a3 = hfma2(v.w, E2a[4 * j + 3], a3);
            b0 = hfma2(v.x, E2b[4 * j + 0], b0);
            b1 = hfma2(v.y, E2b[4 * j + 1], b1);
            b2 = hfma2(v.z, E2b[4 * j + 2], b2);
            b3 = hfma2(v.w, E2b[4 * j + 3], b3);
        }
        const unsigned sA = hadd2(hadd2(a0, a1), hadd2(a2, a3));
        const unsigned sB = hadd2(hadd2(b0, b1), hadd2(b2, b3));
        dA = bf_lo(sA) + bf_hi(sA);
        dB = bf_lo(sB) + bf_hi(sB);
    };

    // fused two-chain matvec: both dependency trees interleaved for ILP
    auto matvec2 = [&](float& dA0, float& dA1, unsigned& w0A,
                       float& dB0, float& dB1, unsigned& w0B) {
        const uint4* pA = reinterpret_cast<const uint4*>(qA[pbA]);
        const uint4* pB = reinterpret_cast<const uint4*>(qB[pbB]);
        unsigned xa0, xa1, xa2, xa3, ya0, ya1, ya2, ya3;
        unsigned xb0, xb1, xb2, xb3, yb0, yb1, yb2, yb3;
        {
            uint4 vA = pA[0], vB = pB[0];
            w0A = vA.x;  w0B = vB.x;
            xa0 = hfma2(vA.x, E2a[0], 0u);  xb0 = hfma2(vB.x, E2a[0], 0u);
            xa1 = hfma2(vA.y, E2a[1], 0u);  xb1 = hfma2(vB.y, E2a[1], 0u);
            xa2 = hfma2(vA.z, E2a[2], 0u);  xb2 = hfma2(vB.z, E2a[2], 0u);
            xa3 = hfma2(vA.w, E2a[3], 0u);  xb3 = hfma2(vB.w, E2a[3], 0u);
            ya0 = hfma2(vA.x, E2b[0], 0u);  yb0 = hfma2(vB.x, E2b[0], 0u);
            ya1 = hfma2(vA.y, E2b[1], 0u);  yb1 = hfma2(vB.y, E2b[1], 0u);
            ya2 = hfma2(vA.z, E2b[2], 0u);  yb2 = hfma2(vB.z, E2b[2], 0u);
            ya3 = hfma2(vA.w, E2b[3], 0u);  yb3 = hfma2(vB.w, E2b[3], 0u);
        }
        #pragma unroll
        for (int j = 1; j < 8; ++j) {
            uint4 vA = pA[j], vB = pB[j];
            xa0 = hfma2(vA.x, E2a[4 * j + 0], xa0);  xb0 = hfma2(vB.x, E2a[4 * j + 0], xb0);
            xa1 = hfma2(vA.y, E2a[4 * j + 1], xa1);  xb1 = hfma2(vB.y, E2a[4 * j + 1], xb1);
            xa2 = hfma2(vA.z, E2a[4 * j + 2], xa2);  xb2 = hfma2(vB.z, E2a[4 * j + 2], xb2);
            xa3 = hfma2(vA.w, E2a[4 * j + 3], xa3);  xb3 = hfma2(vB.w, E2a[4 * j + 3], xb3);
            ya0 = hfma2(vA.x, E2b[4 * j + 0], ya0);  yb0 = hfma2(vB.x, E2b[4 * j + 0], yb0);
            ya1 = hfma2(vA.y, E2b[4 * j + 1], ya1);  yb1 = hfma2(vB.y, E2b[4 * j + 1], yb1);
            ya2 = hfma2(vA.z, E2b[4 * j + 2], ya2);  yb2 = hfma2(vB.z, E2b[4 * j + 2], yb2);
            ya3 = hfma2(vA.w, E2b[4 * j + 3], ya3);  yb3 = hfma2(vB.w, E2b[4 * j + 3], yb3);
        }
        const unsigned sA0 = hadd2(hadd2(xa0, xa1), hadd2(xa2, xa3));
        const unsigned sA1 = hadd2(hadd2(ya0, ya1), hadd2(ya2, ya3));
        const unsigned sB0 = hadd2(hadd2(xb0, xb1), hadd2(xb2, xb3));
        const unsigned sB1 = hadd2(hadd2(yb0, yb1), hadd2(yb2, yb3));
        dA0 = bf_lo(sA0) + bf_hi(sA0);
        dA1 = bf_lo(sA1) + bf_hi(sA1);
        dB0 = bf_lo(sB0) + bf_hi(sB0);
        dB1 = bf_lo(sB1) + bf_hi(sB1);
    };

    if (isF) {
        // gold first halves of both batches
        float ga = 0.f, gb = 0.f;
        for (int s = lane; s < hA; s += 32) {
            int t1 = tgA[s];
            int t0 = (s == 0) ? START : tgA[s - 1];
            ga += fAp[s * Tt + t1] + trans[t0 * Tt + t1];
        }
        for (int s = lane; s < hB; s += 32) {
            int t1 = tgB[s];
            int t0 = (s == 0) ? START : tgB[s - 1];
            gb += fBp[s * Tt + t1] + trans[t0 * Tt + t1];
        }
        goldA = warp_sum(ga);
        goldB = warp_sum(gb);

        // init both
        const float tS0 = trans[START * Tt];
        const float tSa = trans[START * Tt + to0];
        const float tSb = trans[START * Tt + to0 + 1];
        cA0 = fAp[0] + tS0;
        cB0 = fBp[0] + tS0;
        {
            float2 f0 = *reinterpret_cast<const float2*>(fAp + to0);
            qA[0][lane] = pack_bf2(__expf(f0.x + tSa - cA0), __expf(f0.y + tSb - cA0));
            float2 f1 = *reinterpret_cast<const float2*>(fBp + to0);
            qB[0][lane] = pack_bf2(__expf(f1.x + tSa - cB0), __expf(f1.y + tSb - cB0));
        }

        float2 fpA[PD], fpB[PD];
        #pragma unroll
        for (int r = 0; r < PD; ++r) {
            fpA[r] = *reinterpret_cast<const float2*>(fAp + (1 + r) * Tt + to0);
            fpB[r] = *reinterpret_cast<const float2*>(fBp + (1 + r) * Tt + to0);
        }

        auto fstep2 = [&](float2 fa, float2 fbv) {
            const float eaA = __expf(fa.x),  ebA = __expf(fa.y);
            const float eaB = __expf(fbv.x), ebB = __expf(fbv.y);
            __syncwarp();
            float dA0, dA1, dB0, dB1;
            unsigned w0A, w0B;
            matvec2(dA0, dA1, w0A, dB0, dB1, w0B);
            const unsigned eA = (w0A >> 7) & 0xFFu;
            const unsigned eB = (w0B >> 7) & 0xFFu;
            eSumA += (int)eA - 127;
            eSumB += (int)eB - 127;
            const float scA = __uint_as_float((254u - eA) << 23);
            const float scB = __uint_as_float((254u - eB) << 23);
            curA0 = dA0 * (eaA * scA);  curA1 = dA1 * (ebA * scA);
            curB0 = dB0 * (eaB * scB);  curB1 = dB1 * (ebB * scB);
            pbA ^= 1;  pbB ^= 1;
            qA[pbA][lane] = pack_bf2(curA0, curA1);
            qB[pbB][lane] = pack_bf2(curB0, curB1);
        };
        auto fstep1 = [&](unsigned (*q)[Tt / 2], int& pb, int& eSum,
                          float& c0, float& c1, float2 f) {
            const float ea = __expf(f.x), eb = __expf(f.y);
            __syncwarp();
            float d0, d1;
            unsigned w0;
            matvec1(q[pb], d0, d1, w0);
            const unsigned e = (w0 >> 7) & 0xFFu;
            eSum += (int)e - 127;
            const float sc = __uint_as_float((254u - e) << 23);
            c0 = d0 * (ea * sc);
            c1 = d1 * (eb * sc);
            pb ^= 1;
            q[pb][lane] = pack_bf2(c0, c1);
        };

        const int nmin = (hA < hB) ? hA : hB;
        int s = 1;
        for (; s + (PD - 1) <= nmin; ) {
            #pragma unroll
            for (int r = 0; r < PD; ++r) {
                const float2 fa = fpA[r], fbv = fpB[r];
                fpA[r] = *reinterpret_cast<const float2*>(fAp + (size_t)(s + PD) * Tt + to0);
                fpB[r] = *reinterpret_cast<const float2*>(fBp + (size_t)(s + PD) * Tt + to0);
                fstep2(fa, fbv);
                ++s;
            }
        }
        for (; s <= nmin; ++s) {
            int r = (s - 1) & (PD - 1);
            fstep2(fpA[r], fpB[r]);
        }
        for (int sa = s; sa <= hA; ++sa) {
            int r = (sa - 1) & (PD - 1);
            float2 f = fpA[r];
            fpA[r] = *reinterpret_cast<const float2*>(fAp + (size_t)(sa + PD <= hA ? sa + PD : hA) * Tt + to0);
            fstep1(qA, pbA, eSumA, curA0, curA1, f);
        }
        for (int sb = s; sb <= hB; ++sb) {
            int r = (sb - 1) & (PD - 1);
            float2 f = fpB[r];
            fpB[r] = *reinterpret_cast<const float2*>(fBp + (size_t)(sb + PD <= hB ? sb + PD : hB) * Tt + to0);
            fstep1(qB, pbB, eSumB, curB0, curB1, f);
        }

        // publish P_h for both batches
        g_meet[bA][0][to0] = curA0;  g_meet[bA][0][to0 + 1] = curA1;
        g_meet[bB][0][to0] = curB0;  g_meet[bB][0][to0 + 1] = curB1;
        if (lane == 0) {
            g_meet[bA][0][64] = (float)eSumA; g_meet[bA][0][65] = cA0; g_meet[bA][0][66] = goldA;
            g_meet[bB][0][64] = (float)eSumB; g_meet[bB][0][65] = cB0; g_meet[bB][0][66] = goldB;
        }
    } else {
        // gold second halves + STOP of both batches
        float ga = 0.f, gb = 0.f;
        for (int s = hA + lane; s < LA; s += 32) {
            int t1 = tgA[s];
            int t0 = tgA[s - 1];
            ga += fAp[s * Tt + t1] + trans[t0 * Tt + t1];
        }
        for (int s = hB + lane; s < LB; s += 32) {
            int t1 = tgB[s];
            int t0 = tgB[s - 1];
            gb += fBp[s * Tt + t1] + trans[t0 * Tt + t1];
        }
        goldA = warp_sum(ga) + trans[tgA[LA - 1] * Tt + STOP];
        goldB = warp_sum(gb) + trans[tgB[LB - 1] * Tt + STOP];

        // init: u_{L-1} = Estop (rows of E hold exp(trans[to][STOP]) pair 31 hi)
        const float u0 = bf_hi(E2a[31]);
        const float u1 = bf_hi(E2b[31]);
        curA0 = u0;  curA1 = u1;
        curB0 = u0;  curB1 = u1;
        {
            float2 fa = *reinterpret_cast<const float2*>(fAp + (size_t)(LA - 1) * Tt + to0);
            qA[0][lane] = pack_bf2(u0 * __expf(fa.x), u1 * __expf(fa.y));
            float2 fbv = *reinterpret_cast<const float2*>(fBp + (size_t)(LB - 1) * Tt + to0);
            qB[0][lane] = pack_bf2(u0 * __expf(fbv.x), u1 * __expf(fbv.y));
        }
        const int nA = LA - 1 - hA;
        const int nB = LB - 1 - hB;

        float2 fpA[PD], fpB[PD];
        #pragma unroll
        for (int r = 0; r < PD; ++r) {
            fpA[r] = *reinterpret_cast<const float2*>(fAp + (size_t)(LA - 2 - r) * Tt + to0);
            fpB[r] = *reinterpret_cast<const float2*>(fBp + (size_t)(LB - 2 - r) * Tt + to0);
        }

        auto bstep2 = [&](float2 fa, float2 fbv) {
            const float eaA = __expf(fa.x),  ebA = __expf(fa.y);
            const float eaB = __expf(fbv.x), ebB = __expf(fbv.y);
            __syncwarp();
            float dA0, dA1, dB0, dB1;
            unsigned w0A, w0B;
            matvec2(dA0, dA1, w0A, dB0, dB1, w0B);
            const unsigned eA = (w0A >> 7) & 0xFFu;
            const unsigned eB = (w0B >> 7) & 0xFFu;
            eSumA += (int)eA - 127;
            eSumB += (int)eB - 127;
            const float scA = __uint_as_float((254u - eA) << 23);
            const float scB = __uint_as_float((254u - eB) << 23);
            curA0 = dA0 * scA;  curA1 = dA1 * scA;
            curB0 = dB0 * scB;  curB1 = dB1 * scB;
            pbA ^= 1;  pbB ^= 1;
            qA[pbA][lane] = pack_bf2(curA0 * eaA, curA1 * ebA);
            qB[pbB][lane] = pack_bf2(curB0 * eaB, curB1 * ebB);
        };
        auto bstep1 = [&](unsigned (*q)[Tt / 2], int& pb, int& eSum,
                          float& c0, float& c1, float2 f) {
            const float ea = __expf(f.x), eb = __expf(f.y);
            __syncwarp();
            float d0, d1;
            unsigned w0;
            matvec1(q[pb], d0, d1, w0);
            const unsigned e = (w0 >> 7) & 0xFFu;
            eSum += (int)e - 127;
            const float sc = __uint_as_float((254u - e) << 23);
            c0 = d0 * sc;
            c1 = d1 * sc;
            pb ^= 1;
            q[pb][lane] = pack_bf2(c0 * ea, c1 * eb);
        };

        const int nmin = (nA < nB) ? nA : nB;
        int j = 0;
        for (; j + PD <= nmin; ) {
            #pragma unroll
            for (int r = 0; r < PD; ++r) {
                const float2 fa = fpA[r], fbv = fpB[r];
                fpA[r] = *reinterpret_cast<const float2*>(fAp + (size_t)(LA - 2 - j - PD) * Tt + to0);
                fpB[r] = *reinterpret_cast<const float2*>(fBp + (size_t)(LB - 2 - j - PD) * Tt + to0);
                bstep2(fa, fbv);
                ++j;
            }
        }
        for (; j < nmin; ++j) {
            int r = j & (PD - 1);
            bstep2(fpA[r], fpB[r]);
        }
        for (int ja = j; ja < nA; ++ja) {
            int r = ja & (PD - 1);
            float2 f = fpA[r];
            int nxt = LA - 2 - ja - PD;
            fpA[r] = *reinterpret_cast<const float2*>(fAp + (size_t)(nxt >= 0 ? nxt : 0) * Tt + to0);
            bstep1(qA, pbA, eSumA, curA0, curA1, f);
        }
        for (int jb = j; jb < nB; ++jb) {
            int r = jb & (PD - 1);
            float2 f = fpB[r];
            int nxt = LB - 2 - jb - PD;
            fpB[r] = *reinterpret_cast<const float2*>(fBp + (size_t)(nxt >= 0 ? nxt : 0) * Tt + to0);
            bstep1(qB, pbB, eSumB, curB0, curB1, f);
        }

        // publish u_h for both batches
        g_meet[bA][1][to0] = curA0;  g_meet[bA][1][to0 + 1] = curA1;
        g_meet[bB][1][to0] = curB0;  g_meet[bB][1][to0 + 1] = curB1;
        if (lane == 0) {
            g_meet[bA][1][64] = (float)eSumA; g_meet[bA][1][65] = goldA;
            g_meet[bB][1][64] = (float)eSumB; g_meet[bB][1][65] = goldB;
        }
    }

    // ---- rendezvous per batch: second arriver combines ----
    __threadfence();
    unsigned oA = 0, oB = 0;
    if (lane == 0) {
        oA = atomicAdd(&g_pair[bA], 1u);
        oB = atomicAdd(&g_pair[bB], 1u);
    }
    oA = __shfl_sync(0xffffffffu, oA, 0);
    oB = __shfl_sync(0xffffffffu, oB, 0);

    auto combine = [&](int b) -> unsigned {
        __threadfence();
        const float p0 = ldcg(&g_meet[b][0][to0]);
        const float p1 = ldcg(&g_meet[b][0][to0 + 1]);
        const float u0 = ldcg(&g_meet[b][1][to0]);
        const float u1 = ldcg(&g_meet[b][1][to0 + 1]);
        const float dot = warp_sum(p0 * u0 + p1 * u1);
        unsigned c = 0;
        if (lane == 0) {
            const float eF = ldcg(&g_meet[b][0][64]);
            const float c0 = ldcg(&g_meet[b][0][65]);
            const float gF = ldcg(&g_meet[b][0][66]);
            const float eB = ldcg(&g_meet[b][1][64]);
            const float gB = ldcg(&g_meet[b][1][65]);
            g_partial[b] = c0 + (eF + eB) * LN2 + __logf(dot) - (gF + gB);
            g_pair[b] = 0;                      // reset for graph replay
            __threadfence();
            c = atomicAdd(&g_count, 1u);
        }
        return __shfl_sync(0xffffffffu, c, 0);
    };

    unsigned c1 = 0xfffffffeu, c2 = 0xfffffffeu;
    if (oA == 1u) c1 = combine(bA);
    if (oB == 1u) c2 = combine(bB);

    // ---- last combiner: deterministic fixed-order reduction over batches ----
    if (c1 == (unsigned)(Bb - 1) || c2 == (unsigned)(Bb - 1)) {
        __threadfence();
        float sum = 0.f;
        #pragma unroll
        for (int k = 0; k < Bb / 32; ++k)
            sum += ldcg(&g_partial[lane + k * 32]);
        sum = warp_sum(sum);
        if (lane == 0) {
            out[0] = sum;
            g_count = 0;                        // reset for graph replay
        }
    }
}

extern "C" void kernel_launch(void* const* d_in, const int* in_sizes, int n_in,
                              void* d_out, int out_size)
{
    (void)in_sizes; (void)n_in; (void)out_size;
    const float*         feats = (const float*)d_in[0];
    const unsigned char* mask  = (const unsigned char*)d_in[1];
    const int*           tags  = (const int*)d_in[2];
    const float*         trans = (const float*)d_in[3];

    crf_kernel<<<Bb, 32>>>(feats, mask, tags, trans, (float*)d_out);
}